// round 10
// baseline (speedup 1.0000x reference)
#include <cuda_runtime.h>
#include <cuda_bf16.h>
#include <stdint.h>
#include <math.h>

#define Bn   4
#define Tn   2048
#define En   1024
#define Hn   16
#define HDn  64
#define Mn   (Bn * Tn)          // 8192
#define QKVN (3 * En)           // 3072
#define GK   3072               // split K' = 3*E for bf16x3 trick

// ---------------- scratch (__device__ globals; no cudaMalloc allowed) -------
__device__ float g_qkv[(size_t)Mn * QKVN];            // 96 MB fp32
__device__ float g_ctx[(size_t)Mn * En];              // 32 MB fp32
__device__ __nv_bfloat16 g_xs [(size_t)Mn * GK];      // 48 MB  x split
__device__ __nv_bfloat16 g_ws [(size_t)QKVN * GK];    // 18 MB  qkv_w split
__device__ __nv_bfloat16 g_cs [(size_t)Mn * GK];      // 48 MB  ctx split
__device__ __nv_bfloat16 g_pws[(size_t)En * GK];      //  6 MB  proj_w split

// ---------------- helpers (sm_80/90 feature set only) -----------------------
__device__ __forceinline__ uint32_t smem_u32(const void* p) {
    uint32_t a;
    asm("{ .reg .u64 t; cvta.to.shared.u64 t, %1; cvt.u32.u64 %0, t; }"
        : "=r"(a) : "l"(p));
    return a;
}
__device__ __forceinline__ void cp16(uint32_t saddr, const void* g) {
    asm volatile("cp.async.cg.shared.global [%0], [%1], 16;"
                 :: "r"(saddr), "l"(g));
}
template <int N>
__device__ __forceinline__ void cp_wait() {
    asm volatile("cp.async.wait_group %0;" :: "n"(N) : "memory");
}
__device__ __forceinline__ void cp_commit() {
    asm volatile("cp.async.commit_group;" ::: "memory");
}
__device__ __forceinline__ void ldsm4(uint32_t& r0, uint32_t& r1,
                                      uint32_t& r2, uint32_t& r3,
                                      uint32_t addr) {
    asm volatile("ldmatrix.sync.aligned.m8n8.x4.shared.b16 {%0,%1,%2,%3}, [%4];"
                 : "=r"(r0), "=r"(r1), "=r"(r2), "=r"(r3) : "r"(addr));
}
__device__ __forceinline__ void ldsm2(uint32_t& r0, uint32_t& r1,
                                      uint32_t addr) {
    asm volatile("ldmatrix.sync.aligned.m8n8.x2.shared.b16 {%0,%1}, [%2];"
                 : "=r"(r0), "=r"(r1) : "r"(addr));
}
__device__ __forceinline__ void mma16816(float* d, const uint32_t* a,
                                         uint32_t b0, uint32_t b1) {
    asm volatile(
        "mma.sync.aligned.m16n8k16.row.col.f32.bf16.bf16.f32 "
        "{%0,%1,%2,%3}, {%4,%5,%6,%7}, {%8,%9}, {%0,%1,%2,%3};"
        : "+f"(d[0]), "+f"(d[1]), "+f"(d[2]), "+f"(d[3])
        : "r"(a[0]), "r"(a[1]), "r"(a[2]), "r"(a[3]), "r"(b0), "r"(b1));
}
__device__ __forceinline__ uint32_t sw128(uint32_t off) {
    return off ^ ((off >> 3) & 0x70);
}
// tf32 helpers
__device__ __forceinline__ uint32_t f2tf(float x) {
    uint32_t r;
    asm("cvt.rna.tf32.f32 %0, %1;" : "=r"(r) : "f"(x));
    return r;
}
__device__ __forceinline__ float f2tf_f(float x) {
    return __uint_as_float(f2tf(x));
}
__device__ __forceinline__ void mma_tf32(float* d, uint32_t a0, uint32_t a1,
                                         uint32_t a2, uint32_t a3,
                                         uint32_t b0, uint32_t b1) {
    asm volatile(
        "mma.sync.aligned.m16n8k8.row.col.f32.tf32.tf32.f32 "
        "{%0,%1,%2,%3}, {%4,%5,%6,%7}, {%8,%9}, {%0,%1,%2,%3};"
        : "+f"(d[0]), "+f"(d[1]), "+f"(d[2]), "+f"(d[3])
        : "r"(a0), "r"(a1), "r"(a2), "r"(a3), "r"(b0), "r"(b1));
}

// ---------------------------------------------------------------------------
// bf16x3 split conversion
// ---------------------------------------------------------------------------
struct bf16x4 { __nv_bfloat162 a, b; };

__global__ void split3_kernel(const float* __restrict__ in,
                              __nv_bfloat16* __restrict__ out, int lo_sec) {
    size_t i = ((size_t)blockIdx.x * blockDim.x + threadIdx.x) * 4;
    size_t row = i >> 10;          // K = 1024
    int col = (int)(i & 1023);
    float4 v = *(const float4*)(in + i);
    float xs[4] = {v.x, v.y, v.z, v.w};
    __nv_bfloat16 h[4], l[4];
#pragma unroll
    for (int j = 0; j < 4; j++) {
        h[j] = __float2bfloat16_rn(xs[j]);
        l[j] = __float2bfloat16_rn(xs[j] - __bfloat162float(h[j]));
    }
    bf16x4 hv, lv;
    hv.a = __nv_bfloat162(h[0], h[1]); hv.b = __nv_bfloat162(h[2], h[3]);
    lv.a = __nv_bfloat162(l[0], l[1]); lv.b = __nv_bfloat162(l[2], l[3]);
    __nv_bfloat16* o = out + row * GK;
    *(bf16x4*)(o + col) = hv;
    *(bf16x4*)(o + (3 - lo_sec) * 1024 + col) = hv;
    *(bf16x4*)(o + lo_sec * 1024 + col) = lv;
}

// ---------------------------------------------------------------------------
// HMMA bf16 GEMM — 3-stage cp.async pipeline (2 groups in flight).
// Stage s buffer at s*32768: A tile [0,16K), B tile [16K,32K).
// ---------------------------------------------------------------------------
#define GEMM_SMEM (3 * 32768)

__global__ __launch_bounds__(256, 2)
void gemm_hmma(const __nv_bfloat16* __restrict__ A,
               const __nv_bfloat16* __restrict__ B,
               const float* __restrict__ bias,
               float* __restrict__ C, int Np) {
    extern __shared__ char gsm[];
    uint32_t sb = smem_u32(gsm);

    int tid = threadIdx.x;
    int lane = tid & 31;
    int wid = tid >> 5;
    int wm = wid & 3;
    int wn = wid >> 2;
    int m0 = blockIdx.y * 128;
    int n0 = blockIdx.x * 128;

    uint32_t a_soff[4]; const char* a_g[4];
    uint32_t b_soff[4]; const char* b_g[4];
#pragma unroll
    for (int i = 0; i < 4; i++) {
        int c = tid + i * 256;
        int row = c >> 3, ch = c & 7;
        uint32_t off = row * 128 + ch * 16;
        a_soff[i] = sw128(off);
        b_soff[i] = sw128(off) + 16384;
        a_g[i] = (const char*)(A + (size_t)(m0 + row) * GK + ch * 8);
        b_g[i] = (const char*)(B + (size_t)(n0 + row) * GK + ch * 8);
    }

    uint32_t rA = wm * 32 + (lane & 7) + ((lane >> 3) & 1) * 8;
    uint32_t kA = ((lane >> 4) & 1) * 16;
    uint32_t rB = wn * 64 + (lane & 7) + ((lane >> 3) & 1) * 8;
    uint32_t kB = ((lane >> 4) & 1) * 16;
    // NOTE: keep exact round-4 fragment mapping:
    rA = wm * 32 + (lane & 7) + ((lane >> 3) & 1) * 8;
    kA = ((lane >> 4) & 1) * 16;
    rB = wn * 64 + (lane & 7) + ((lane >> 4) & 1) * 8;
    kB = ((lane >> 3) & 1) * 16;

    float acc[2][8][4];
#pragma unroll
    for (int mt = 0; mt < 2; mt++)
#pragma unroll
        for (int t = 0; t < 8; t++)
#pragma unroll
            for (int j = 0; j < 4; j++) acc[mt][t][j] = 0.0f;

    const int NS = GK / 64;   // 48

    // prologue: stages 0..2
#pragma unroll
    for (int s = 0; s < 3; s++) {
        uint32_t base = sb + s * 32768;
        size_t goff = (size_t)s * 128;
#pragma unroll
        for (int i = 0; i < 4; i++) cp16(base + a_soff[i], a_g[i] + goff);
#pragma unroll
        for (int i = 0; i < 4; i++) cp16(base + b_soff[i], b_g[i] + goff);
        cp_commit();
    }

    int buf = 0;
    for (int s = 0; s < NS; s++) {
        if (s + 3 < NS) cp_wait<2>(); else cp_wait<0>();
        __syncthreads();

        uint32_t abase = sb + buf * 32768;
        uint32_t bbase = abase + 16384;
#pragma unroll
        for (int kk = 0; kk < 4; kk++) {
            uint32_t a[2][4];
#pragma unroll
            for (int mt = 0; mt < 2; mt++) {
                uint32_t off = (rA + mt * 16) * 128 + kk * 32 + kA;
                ldsm4(a[mt][0], a[mt][1], a[mt][2], a[mt][3], abase + sw128(off));
            }
#pragma unroll
            for (int nt = 0; nt < 4; nt++) {
                uint32_t off = (rB + nt * 16) * 128 + kk * 32 + kB;
                uint32_t b0, b1, b2, b3;
                ldsm4(b0, b1, b2, b3, bbase + sw128(off));
                mma16816(acc[0][nt * 2 + 0], a[0], b0, b1);
                mma16816(acc[0][nt * 2 + 1], a[0], b2, b3);
                mma16816(acc[1][nt * 2 + 0], a[1], b0, b1);
                mma16816(acc[1][nt * 2 + 1], a[1], b2, b3);
            }
        }
        __syncthreads();

        if (s + 3 < NS) {
            uint32_t base = sb + buf * 32768;
            size_t goff = (size_t)(s + 3) * 128;
#pragma unroll
            for (int i = 0; i < 4; i++) cp16(base + a_soff[i], a_g[i] + goff);
#pragma unroll
            for (int i = 0; i < 4; i++) cp16(base + b_soff[i], b_g[i] + goff);
            cp_commit();
        }
        buf = (buf + 1 == 3) ? 0 : buf + 1;
    }

#pragma unroll
    for (int mt = 0; mt < 2; mt++) {
#pragma unroll
        for (int t = 0; t < 8; t++) {
            int row = m0 + wm * 32 + mt * 16 + (lane >> 2);
            int col = n0 + wn * 64 + t * 8 + (lane & 3) * 2;
            float2 bv = *(const float2*)(bias + col);
            float* p0 = C + (size_t)row * Np + col;
            float2 v0 = { acc[mt][t][0] + bv.x, acc[mt][t][1] + bv.y };
            *(float2*)p0 = v0;
            float* p1 = p0 + 8 * (size_t)Np;
            float2 v1 = { acc[mt][t][2] + bv.x, acc[mt][t][3] + bv.y };
            *(float2*)p1 = v1;
        }
    }
}

// ---------------------------------------------------------------------------
// Flash attention, tf32 HMMA + ldmatrix.
// Block = 256 threads / 8 warps = 128 q rows; warp M-tile = 16 rows.
// 2 CTAs/SM (regs capped 128, smem 104.7KB x2 = 209KB) -> 16 warps/SM.
// smem: Qs[128][68], Ks[64][68], Ps[128][68], Vt[64][68], Ms[64]
// ---------------------------------------------------------------------------
#define APAD 68
#define ATTN3_SMEM ((128 * APAD + 64 * APAD + 128 * APAD + 64 * APAD + 64) * 4)

__global__ __launch_bounds__(256, 2)
void attn_tc(const float* __restrict__ qkv,
             const unsigned char* __restrict__ mask,
             float* __restrict__ ctx) {
    extern __shared__ float sm2[];
    float* Qs = sm2;                    // [128][APAD]
    float* Ks = Qs + 128 * APAD;        // [64][APAD]
    float* Ps = Ks + 64 * APAD;         // [128][APAD]
    float* Vt = Ps + 128 * APAD;        // [64][APAD]  Vt[d][kv]
    float* Ms = Vt + 64 * APAD;         // [64]

    int tid = threadIdx.x;
    int lane = tid & 31;
    int w = tid >> 5;                   // 0..7
    int b  = blockIdx.y >> 4;
    int h  = blockIdx.y & 15;
    int q0 = blockIdx.x * 128;
    int wrow = w * 16;

    const float* qb = qkv + (size_t)b * Tn * QKVN + h * HDn;
    const float* kb = qb + En;
    const float* vb = qb + 2 * En;

    // ---- Q fill: 128 rows, scaled 1/8, tf32 ----
#pragma unroll
    for (int it = 0; it < 8; it++) {
        int idx = tid + it * 256;          // 0..2047
        int r = idx >> 4;
        int c4 = (idx & 15) * 4;
        float4 v = *(const float4*)(qb + (size_t)(q0 + r) * QKVN + c4);
        v.x = f2tf_f(v.x * 0.125f); v.y = f2tf_f(v.y * 0.125f);
        v.z = f2tf_f(v.z * 0.125f); v.w = f2tf_f(v.w * 0.125f);
        *(float4*)&Qs[r * APAD + c4] = v;
    }

    int r0 = lane >> 2;
    int cq = lane & 3;

    // ldmatrix per-lane addresses (bytes)
    uint32_t sb = smem_u32(sm2);
    int t  = lane >> 3;                       // 0..3
    int arow = (t & 1) * 8 + (lane & 7);
    int acol = (t >> 1) * 4;
    uint32_t qs_a = sb + (uint32_t)(((wrow + arow) * APAD + acol) * 4);
    uint32_t ps_a = sb + (uint32_t)((128 * APAD + 64 * APAD) * 4)
                       + (uint32_t)(((wrow + arow) * APAD + acol) * 4);
    int brow = lane & 7;
    int bsel = (lane >> 3) & 1;
    uint32_t ks_b = sb + (uint32_t)((128 * APAD) * 4)
                       + (uint32_t)((brow * APAD + bsel * 4) * 4);
    uint32_t vt_b = sb + (uint32_t)((128 * APAD + 64 * APAD + 128 * APAD) * 4)
                       + (uint32_t)((brow * APAD + bsel * 4) * 4);
    const uint32_t N_STEP  = 8 * APAD * 4;    // bytes per n-tile (B)

    float oacc[8][4];
#pragma unroll
    for (int n = 0; n < 8; n++)
#pragma unroll
        for (int j = 0; j < 4; j++) oacc[n][j] = 0.0f;
    float m0f = -1e30f, m1f = -1e30f, l0 = 0.0f, l1 = 0.0f;

    for (int kv0 = 0; kv0 < Tn; kv0 += 64) {
        // ---- K fill (tf32) ----
#pragma unroll
        for (int it = 0; it < 4; it++) {
            int idx = tid + it * 256;          // 0..1023
            int r = idx >> 4;
            int c4 = (idx & 15) * 4;
            float4 v = *(const float4*)(kb + (size_t)(kv0 + r) * QKVN + c4);
            v.x = f2tf_f(v.x); v.y = f2tf_f(v.y);
            v.z = f2tf_f(v.z); v.w = f2tf_f(v.w);
            *(float4*)&Ks[r * APAD + c4] = v;
        }
        // ---- V fill transposed: Vt[d][kv] ----
#pragma unroll
        for (int it = 0; it < 4; it++) {
            int idx = tid + it * 256;
            int r = idx & 63;                 // kv row
            int c4 = (idx >> 6) * 4;          // d base
            float4 v = *(const float4*)(vb + (size_t)(kv0 + r) * QKVN + c4);
            Vt[(c4 + 0) * APAD + r] = f2tf_f(v.x);
            Vt[(c4 + 1) * APAD + r] = f2tf_f(v.y);
            Vt[(c4 + 2) * APAD + r] = f2tf_f(v.z);
            Vt[(c4 + 3) * APAD + r] = f2tf_f(v.w);
        }
        if (tid < 64)
            Ms[tid] = mask[b * Tn + kv0 + tid] ? -1e30f : 0.0f;
        __syncthreads();

        // ---- S = Q K^T ----
        float sacc[8][4];
#pragma unroll
        for (int n = 0; n < 8; n++)
#pragma unroll
            for (int j = 0; j < 4; j++) sacc[n][j] = 0.0f;

#pragma unroll
        for (int k = 0; k < 8; k++) {
            uint32_t a[4];
            ldsm4(a[0], a[1], a[2], a[3], qs_a + k * 32);
#pragma unroll
            for (int n = 0; n < 8; n++) {
                uint32_t b0, b1;
                ldsm2(b0, b1, ks_b + n * N_STEP + k * 32);
                mma_tf32(sacc[n], a[0], a[1], a[2], a[3], b0, b1);
            }
        }

        // ---- mask + online softmax ----
        float mx0 = -1e30f, mx1 = -1e30f;
#pragma unroll
        for (int n = 0; n < 8; n++) {
            int c = n * 8 + cq * 2;
            float ma = Ms[c], mb2 = Ms[c + 1];
            sacc[n][0] += ma; sacc[n][1] += mb2;
            sacc[n][2] += ma; sacc[n][3] += mb2;
            mx0 = fmaxf(mx0, fmaxf(sacc[n][0], sacc[n][1]));
            mx1 = fmaxf(mx1, fmaxf(sacc[n][2], sacc[n][3]));
        }
        mx0 = fmaxf(mx0, __shfl_xor_sync(0xffffffffu, mx0, 1));
        mx0 = fmaxf(mx0, __shfl_xor_sync(0xffffffffu, mx0, 2));
        mx1 = fmaxf(mx1, __shfl_xor_sync(0xffffffffu, mx1, 1));
        mx1 = fmaxf(mx1, __shfl_xor_sync(0xffffffffu, mx1, 2));

        float nm0 = fmaxf(m0f, mx0), nm1 = fmaxf(m1f, mx1);
        float al0 = __expf(m0f - nm0), al1 = __expf(m1f - nm1);
        float rs0 = 0.0f, rs1 = 0.0f;
#pragma unroll
        for (int n = 0; n < 8; n++) {
            sacc[n][0] = __expf(sacc[n][0] - nm0);
            sacc[n][1] = __expf(sacc[n][1] - nm0);
            sacc[n][2] = __expf(sacc[n][2] - nm1);
            sacc[n][3] = __expf(sacc[n][3] - nm1);
            rs0 += sacc[n][0] + sacc[n][1];
            rs1 += sacc[n][2] + sacc[n][3];
        }
        rs0 += __shfl_xor_sync(0xffffffffu, rs0, 1);
        rs0 += __shfl_xor_sync(0xffffffffu, rs0, 2);
        rs1 += __shfl_xor_sync(0xffffffffu, rs1, 1);
        rs1 += __shfl_xor_sync(0xffffffffu, rs1, 2);

        l0 = l0 * al0 + rs0;  m0f = nm0;
        l1 = l1 * al1 + rs1;  m1f = nm1;
#pragma unroll
        for (int n = 0; n < 8; n++) {
            oacc[n][0] *= al0; oacc[n][1] *= al0;
            oacc[n][2] *= al1; oacc[n][3] *= al1;
        }

        // ---- store P (tf32; warp-private rows) ----
        {
            int pr0 = (wrow + r0) * APAD;
            int pr1 = pr0 + 8 * APAD;
#pragma unroll
            for (int n = 0; n < 8; n++) {
                int c = n * 8 + cq * 2;
                *(float2*)&Ps[pr0 + c] =
                    make_float2(f2tf_f(sacc[n][0]), f2tf_f(sacc[n][1]));
                *(float2*)&Ps[pr1 + c] =
                    make_float2(f2tf_f(sacc[n][2]), f2tf_f(sacc[n][3]));
            }
        }
        __syncwarp();

        // ---- O += P V ----
#pragma unroll
        for (int k = 0; k < 8; k++) {
            uint32_t p[4];
            ldsm4(p[0], p[1], p[2], p[3], ps_a + k * 32);
#pragma unroll
            for (int n = 0; n < 8; n++) {
                uint32_t b0, b1;
                ldsm2(b0, b1, vt_b + n * N_STEP + k * 32);
                mma_tf32(oacc[n], p[0], p[1], p[2], p[3], b0, b1);
            }
        }
        __syncthreads();
    }

    // ---- epilogue ----
    float inv0 = 1.0f / l0, inv1 = 1.0f / l1;
    int row = q0 + wrow + r0;
#pragma unroll
    for (int n = 0; n < 8; n++) {
        int col = h * HDn + n * 8 + cq * 2;
        float* p0 = &ctx[((size_t)b * Tn + row) * En + col];
        *(float2*)p0 = make_float2(oacc[n][0] * inv0, oacc[n][1] * inv0);
        float* p1 = &ctx[((size_t)b * Tn + row + 8) * En + col];
        *(float2*)p1 = make_float2(oacc[n][2] * inv1, oacc[n][3] * inv1);
    }
}

// ---------------------------------------------------------------------------
extern "C" void kernel_launch(void* const* d_in, const int* in_sizes, int n_in,
                              void* d_out, int out_size) {
    const float*         x      = (const float*)d_in[0];
    const unsigned char* mask   = (const unsigned char*)d_in[1];
    const float*         qkv_w  = (const float*)d_in[2];
    const float*         qkv_b  = (const float*)d_in[3];
    const float*         proj_w = (const float*)d_in[4];
    const float*         proj_b = (const float*)d_in[5];
    float*               out    = (float*)d_out;

    float *qkv_s, *ctx_s;
    __nv_bfloat16 *xs, *ws, *cs, *pws;
    cudaGetSymbolAddress((void**)&qkv_s, g_qkv);
    cudaGetSymbolAddress((void**)&ctx_s, g_ctx);
    cudaGetSymbolAddress((void**)&xs,  g_xs);
    cudaGetSymbolAddress((void**)&ws,  g_ws);
    cudaGetSymbolAddress((void**)&cs,  g_cs);
    cudaGetSymbolAddress((void**)&pws, g_pws);

    cudaFuncSetAttribute(gemm_hmma,
                         cudaFuncAttributeMaxDynamicSharedMemorySize, GEMM_SMEM);
    cudaFuncSetAttribute(attn_tc,
                         cudaFuncAttributeMaxDynamicSharedMemorySize, ATTN3_SMEM);

    // 1) split x and qkv_w into bf16x3
    split3_kernel<<<(size_t)Mn * En / 4 / 256, 256>>>(x, xs, 1);
    split3_kernel<<<(size_t)QKVN * En / 4 / 256, 256>>>(qkv_w, ws, 2);

    // 2) QKV GEMM
    {
        dim3 grid(QKVN / 128, Mn / 128);
        gemm_hmma<<<grid, 256, GEMM_SMEM>>>(xs, ws, qkv_b, qkv_s, QKVN);
    }

    // 3) attention (tf32 tensor cores; 8 warps, 128 q-rows/block)
    {
        dim3 grid(Tn / 128, Bn * Hn);
        attn_tc<<<grid, 256, ATTN3_SMEM>>>(qkv_s, mask, ctx_s);
    }

    // 4) split ctx and proj_w
    split3_kernel<<<(size_t)Mn * En / 4 / 256, 256>>>(ctx_s, cs, 1);
    split3_kernel<<<(size_t)En * En / 4 / 256, 256>>>(proj_w, pws, 2);

    // 5) proj GEMM
    {
        dim3 grid(En / 128, Mn / 128);
        gemm_hmma<<<grid, 256, GEMM_SMEM>>>(cs, pws, proj_b, out, En);
    }
}

// round 11
// speedup vs baseline: 1.1465x; 1.1465x over previous
#include <cuda_runtime.h>
#include <cuda_bf16.h>
#include <stdint.h>
#include <math.h>

#define Bn   4
#define Tn   2048
#define En   1024
#define Hn   16
#define HDn  64
#define Mn   (Bn * Tn)          // 8192
#define QKVN (3 * En)           // 3072

// ---------------- scratch (__device__ globals; no cudaMalloc allowed) -------
__device__ float g_qkv[(size_t)Mn * QKVN];            // 96 MB fp32
__device__ float g_ctx[(size_t)Mn * En];              // 32 MB fp32

// ---------------- helpers ----------------------------------------------------
__device__ __forceinline__ uint32_t smem_u32(const void* p) {
    uint32_t a;
    asm("{ .reg .u64 t; cvta.to.shared.u64 t, %1; cvt.u32.u64 %0, t; }"
        : "=r"(a) : "l"(p));
    return a;
}
__device__ __forceinline__ void ldsm4(uint32_t& r0, uint32_t& r1,
                                      uint32_t& r2, uint32_t& r3,
                                      uint32_t addr) {
    asm volatile("ldmatrix.sync.aligned.m8n8.x4.shared.b16 {%0,%1,%2,%3}, [%4];"
                 : "=r"(r0), "=r"(r1), "=r"(r2), "=r"(r3) : "r"(addr));
}
__device__ __forceinline__ void ldsm2(uint32_t& r0, uint32_t& r1,
                                      uint32_t addr) {
    asm volatile("ldmatrix.sync.aligned.m8n8.x2.shared.b16 {%0,%1}, [%2];"
                 : "=r"(r0), "=r"(r1) : "r"(addr));
}
// tf32 helpers
__device__ __forceinline__ uint32_t f2tf(float x) {
    uint32_t r;
    asm("cvt.rna.tf32.f32 %0, %1;" : "=r"(r) : "f"(x));
    return r;
}
__device__ __forceinline__ float f2tf_f(float x) {
    return __uint_as_float(f2tf(x));
}
__device__ __forceinline__ void mma_tf32(float* d, uint32_t a0, uint32_t a1,
                                         uint32_t a2, uint32_t a3,
                                         uint32_t b0, uint32_t b1) {
    asm volatile(
        "mma.sync.aligned.m16n8k8.row.col.f32.tf32.tf32.f32 "
        "{%0,%1,%2,%3}, {%4,%5,%6,%7}, {%8,%9}, {%0,%1,%2,%3};"
        : "+f"(d[0]), "+f"(d[1]), "+f"(d[2]), "+f"(d[3])
        : "r"(a0), "r"(a1), "r"(a2), "r"(a3), "r"(b0), "r"(b1));
}

// ---------------------------------------------------------------------------
// tf32 GEMM: C[M,Np] = A[M,1024] @ W[Np,1024]^T + bias.  fp32 in/out.
// CTA 128x128, BK=32, 8 warps (4m x 2n), warp tile 32x64.
// Fill: LDG float4 -> cvt.rna.tf32 -> STS.  Double buffered, 1 sync/stage.
// Fragments via ldmatrix (tf32-as-8x4x32b trick, layout verified in attn).
// ---------------------------------------------------------------------------
#define GT_APAD 36
#define GT_TILE (128 * GT_APAD)                 // floats per operand tile
#define GEMM_TF32_SMEM (2 * 2 * GT_TILE * 4)    // 73728 B

__global__ __launch_bounds__(256, 2)
void gemm_tf32(const float* __restrict__ A, const float* __restrict__ W,
               const float* __restrict__ bias, float* __restrict__ C, int Np) {
    extern __shared__ float gt[];
    const int K = 1024;
    int tid = threadIdx.x;
    int lane = tid & 31;
    int wid = tid >> 5;
    int wm = wid & 3;                 // m offset wm*32
    int wn = wid >> 2;                // n offset wn*64
    int m0 = blockIdx.y * 128;
    int n0 = blockIdx.x * 128;

    // fill slots: 1024 float4s per operand tile; 4 per thread
    int fr[4], fc[4];
    const float* Ag[4]; const float* Wg[4];
#pragma unroll
    for (int i = 0; i < 4; i++) {
        int c = tid + i * 256;        // 0..1023
        fr[i] = c >> 3;               // row 0..127
        fc[i] = (c & 7) * 4;          // col 0,4,...,28
        Ag[i] = A + (size_t)(m0 + fr[i]) * K + fc[i];
        Wg[i] = W + (size_t)(n0 + fr[i]) * K + fc[i];
    }

    // ldmatrix per-lane addresses
    uint32_t sb = smem_u32(gt);
    int t = lane >> 3;
    int arow = (t & 1) * 8 + (lane & 7);
    int acol = (t >> 1) * 4;
    uint32_t a_base = sb + (uint32_t)(((wm * 32 + arow) * GT_APAD + acol) * 4);
    uint32_t b_base = sb + (uint32_t)(GT_TILE * 4)
                    + (uint32_t)(((wn * 64 + (lane & 7)) * GT_APAD
                                  + ((lane >> 3) & 1) * 4) * 4);
    const uint32_t MT_STEP  = 16 * GT_APAD * 4;
    const uint32_t N_STEP   = 8 * GT_APAD * 4;
    const uint32_t BUF_STEP = 2 * GT_TILE * 4;

    float acc[2][8][4];
#pragma unroll
    for (int mt = 0; mt < 2; mt++)
#pragma unroll
        for (int nt = 0; nt < 8; nt++)
#pragma unroll
            for (int j = 0; j < 4; j++) acc[mt][nt][j] = 0.0f;

    const int NK = K / 32;            // 32 stages

    // prologue: stage 0 -> buf0
    float4 pa[4], pb[4];
#pragma unroll
    for (int i = 0; i < 4; i++) { pa[i] = *(const float4*)Ag[i];
                                  pb[i] = *(const float4*)Wg[i]; }
#pragma unroll
    for (int i = 0; i < 4; i++) {
        float* da = &gt[fr[i] * GT_APAD + fc[i]];
        da[0] = f2tf_f(pa[i].x); da[1] = f2tf_f(pa[i].y);
        da[2] = f2tf_f(pa[i].z); da[3] = f2tf_f(pa[i].w);
        float* db = &gt[GT_TILE + fr[i] * GT_APAD + fc[i]];
        db[0] = f2tf_f(pb[i].x); db[1] = f2tf_f(pb[i].y);
        db[2] = f2tf_f(pb[i].z); db[3] = f2tf_f(pb[i].w);
    }
    __syncthreads();

    for (int s = 0; s < NK; s++) {
        int buf = s & 1;
        // prefetch stage s+1 into registers (latency hidden by compute)
        if (s + 1 < NK) {
            int off = (s + 1) * 32;
#pragma unroll
            for (int i = 0; i < 4; i++) {
                pa[i] = *(const float4*)(Ag[i] + off);
                pb[i] = *(const float4*)(Wg[i] + off);
            }
        }
        // compute current buffer
        uint32_t ab = a_base + buf * BUF_STEP;
        uint32_t bb = b_base + buf * BUF_STEP;
#pragma unroll
        for (int kk = 0; kk < 4; kk++) {
            uint32_t a0[4], a1[4];
            ldsm4(a0[0], a0[1], a0[2], a0[3], ab + kk * 32);
            ldsm4(a1[0], a1[1], a1[2], a1[3], ab + MT_STEP + kk * 32);
#pragma unroll
            for (int nt = 0; nt < 8; nt++) {
                uint32_t b0, b1;
                ldsm2(b0, b1, bb + nt * N_STEP + kk * 32);
                mma_tf32(acc[0][nt], a0[0], a0[1], a0[2], a0[3], b0, b1);
                mma_tf32(acc[1][nt], a1[0], a1[1], a1[2], a1[3], b0, b1);
            }
        }
        // store next stage into the other buffer (safe: last read 2 stages ago)
        if (s + 1 < NK) {
            int nb = buf ^ 1;
            float* base = gt + nb * 2 * GT_TILE;
#pragma unroll
            for (int i = 0; i < 4; i++) {
                float* da = base + fr[i] * GT_APAD + fc[i];
                da[0] = f2tf_f(pa[i].x); da[1] = f2tf_f(pa[i].y);
                da[2] = f2tf_f(pa[i].z); da[3] = f2tf_f(pa[i].w);
                float* db = base + GT_TILE + fr[i] * GT_APAD + fc[i];
                db[0] = f2tf_f(pb[i].x); db[1] = f2tf_f(pb[i].y);
                db[2] = f2tf_f(pb[i].z); db[3] = f2tf_f(pb[i].w);
            }
        }
        __syncthreads();
    }

    // epilogue
#pragma unroll
    for (int mt = 0; mt < 2; mt++) {
#pragma unroll
        for (int nt = 0; nt < 8; nt++) {
            int row = m0 + wm * 32 + mt * 16 + (lane >> 2);
            int col = n0 + wn * 64 + nt * 8 + (lane & 3) * 2;
            float2 bv = *(const float2*)(bias + col);
            float* p0 = C + (size_t)row * Np + col;
            *(float2*)p0 = make_float2(acc[mt][nt][0] + bv.x,
                                       acc[mt][nt][1] + bv.y);
            float* p1 = p0 + 8 * (size_t)Np;
            *(float2*)p1 = make_float2(acc[mt][nt][2] + bv.x,
                                       acc[mt][nt][3] + bv.y);
        }
    }
}

// ---------------------------------------------------------------------------
// Flash attention — round-9 version verbatim (best measured: 603 us).
// tf32 HMMA, ldmatrix fragments, warp M-tile = 32 rows.
// Block = 128 threads / 4 warps = 128 q rows; KV tiles of 64.
// ---------------------------------------------------------------------------
#define APAD 68
#define ATTN3_SMEM ((128 * APAD + 64 * APAD + 128 * APAD + 64 * APAD + 64) * 4)

__global__ __launch_bounds__(128)
void attn_tc(const float* __restrict__ qkv,
             const unsigned char* __restrict__ mask,
             float* __restrict__ ctx) {
    extern __shared__ float sm2[];
    float* Qs = sm2;                    // [128][APAD]
    float* Ks = Qs + 128 * APAD;        // [64][APAD]
    float* Ps = Ks + 64 * APAD;         // [128][APAD]
    float* Vt = Ps + 128 * APAD;        // [64][APAD]  Vt[d][kv]
    float* Ms = Vt + 64 * APAD;         // [64]

    int tid = threadIdx.x;
    int lane = tid & 31;
    int w = tid >> 5;
    int b  = blockIdx.y >> 4;
    int h  = blockIdx.y & 15;
    int q0 = blockIdx.x * 128;
    int wrow = w * 32;

    const float* qb = qkv + (size_t)b * Tn * QKVN + h * HDn;
    const float* kb = qb + En;
    const float* vb = qb + 2 * En;

#pragma unroll
    for (int it = 0; it < 16; it++) {
        int idx = tid + it * 128;
        int r = idx >> 4;
        int c4 = (idx & 15) * 4;
        float4 v = *(const float4*)(qb + (size_t)(q0 + r) * QKVN + c4);
        v.x = f2tf_f(v.x * 0.125f); v.y = f2tf_f(v.y * 0.125f);
        v.z = f2tf_f(v.z * 0.125f); v.w = f2tf_f(v.w * 0.125f);
        *(float4*)&Qs[r * APAD + c4] = v;
    }

    int r0 = lane >> 2;
    int cq = lane & 3;

    uint32_t sb = smem_u32(sm2);
    int t  = lane >> 3;
    int arow = (t & 1) * 8 + (lane & 7);
    int acol = (t >> 1) * 4;
    uint32_t qs_a = sb + (uint32_t)(((wrow + arow) * APAD + acol) * 4);
    uint32_t ps_a = sb + (uint32_t)((128 * APAD + 64 * APAD) * 4)
                       + (uint32_t)(((wrow + arow) * APAD + acol) * 4);
    int brow = lane & 7;
    int bsel = (lane >> 3) & 1;
    uint32_t ks_b = sb + (uint32_t)((128 * APAD) * 4)
                       + (uint32_t)((brow * APAD + bsel * 4) * 4);
    uint32_t vt_b = sb + (uint32_t)((128 * APAD + 64 * APAD + 128 * APAD) * 4)
                       + (uint32_t)((brow * APAD + bsel * 4) * 4);
    const uint32_t MT_STEP = 16 * APAD * 4;
    const uint32_t N_STEP  = 8 * APAD * 4;

    float oacc[2][8][4];
#pragma unroll
    for (int mt = 0; mt < 2; mt++)
#pragma unroll
        for (int n = 0; n < 8; n++)
#pragma unroll
            for (int j = 0; j < 4; j++) oacc[mt][n][j] = 0.0f;
    float mrow[2][2] = {{-1e30f, -1e30f}, {-1e30f, -1e30f}};
    float lrow[2][2] = {{0.0f, 0.0f}, {0.0f, 0.0f}};

    for (int kv0 = 0; kv0 < Tn; kv0 += 64) {
#pragma unroll
        for (int it = 0; it < 8; it++) {
            int idx = tid + it * 128;
            int r = idx >> 4;
            int c4 = (idx & 15) * 4;
            float4 v = *(const float4*)(kb + (size_t)(kv0 + r) * QKVN + c4);
            v.x = f2tf_f(v.x); v.y = f2tf_f(v.y);
            v.z = f2tf_f(v.z); v.w = f2tf_f(v.w);
            *(float4*)&Ks[r * APAD + c4] = v;
        }
#pragma unroll
        for (int it = 0; it < 8; it++) {
            int idx = tid + it * 128;
            int r = idx & 63;
            int c4 = (idx >> 6) * 4;
            float4 v = *(const float4*)(vb + (size_t)(kv0 + r) * QKVN + c4);
            Vt[(c4 + 0) * APAD + r] = f2tf_f(v.x);
            Vt[(c4 + 1) * APAD + r] = f2tf_f(v.y);
            Vt[(c4 + 2) * APAD + r] = f2tf_f(v.z);
            Vt[(c4 + 3) * APAD + r] = f2tf_f(v.w);
        }
        if (tid < 64)
            Ms[tid] = mask[b * Tn + kv0 + tid] ? -1e30f : 0.0f;
        __syncthreads();

        float sacc[2][8][4];
#pragma unroll
        for (int mt = 0; mt < 2; mt++)
#pragma unroll
            for (int n = 0; n < 8; n++)
#pragma unroll
                for (int j = 0; j < 4; j++) sacc[mt][n][j] = 0.0f;

#pragma unroll
        for (int k = 0; k < 8; k++) {
            uint32_t a0[4], a1[4];
            ldsm4(a0[0], a0[1], a0[2], a0[3], qs_a + k * 32);
            ldsm4(a1[0], a1[1], a1[2], a1[3], qs_a + MT_STEP + k * 32);
#pragma unroll
            for (int n = 0; n < 8; n++) {
                uint32_t b0, b1;
                ldsm2(b0, b1, ks_b + n * N_STEP + k * 32);
                mma_tf32(sacc[0][n], a0[0], a0[1], a0[2], a0[3], b0, b1);
                mma_tf32(sacc[1][n], a1[0], a1[1], a1[2], a1[3], b0, b1);
            }
        }

#pragma unroll
        for (int mt = 0; mt < 2; mt++) {
            float mx0 = -1e30f, mx1 = -1e30f;
#pragma unroll
            for (int n = 0; n < 8; n++) {
                int c = n * 8 + cq * 2;
                float ma = Ms[c], mb2 = Ms[c + 1];
                sacc[mt][n][0] += ma; sacc[mt][n][1] += mb2;
                sacc[mt][n][2] += ma; sacc[mt][n][3] += mb2;
                mx0 = fmaxf(mx0, fmaxf(sacc[mt][n][0], sacc[mt][n][1]));
                mx1 = fmaxf(mx1, fmaxf(sacc[mt][n][2], sacc[mt][n][3]));
            }
            mx0 = fmaxf(mx0, __shfl_xor_sync(0xffffffffu, mx0, 1));
            mx0 = fmaxf(mx0, __shfl_xor_sync(0xffffffffu, mx0, 2));
            mx1 = fmaxf(mx1, __shfl_xor_sync(0xffffffffu, mx1, 1));
            mx1 = fmaxf(mx1, __shfl_xor_sync(0xffffffffu, mx1, 2));

            float nm0 = fmaxf(mrow[mt][0], mx0);
            float nm1 = fmaxf(mrow[mt][1], mx1);
            float al0 = __expf(mrow[mt][0] - nm0);
            float al1 = __expf(mrow[mt][1] - nm1);
            float rs0 = 0.0f, rs1 = 0.0f;
#pragma unroll
            for (int n = 0; n < 8; n++) {
                sacc[mt][n][0] = __expf(sacc[mt][n][0] - nm0);
                sacc[mt][n][1] = __expf(sacc[mt][n][1] - nm0);
                sacc[mt][n][2] = __expf(sacc[mt][n][2] - nm1);
                sacc[mt][n][3] = __expf(sacc[mt][n][3] - nm1);
                rs0 += sacc[mt][n][0] + sacc[mt][n][1];
                rs1 += sacc[mt][n][2] + sacc[mt][n][3];
            }
            rs0 += __shfl_xor_sync(0xffffffffu, rs0, 1);
            rs0 += __shfl_xor_sync(0xffffffffu, rs0, 2);
            rs1 += __shfl_xor_sync(0xffffffffu, rs1, 1);
            rs1 += __shfl_xor_sync(0xffffffffu, rs1, 2);

            lrow[mt][0] = lrow[mt][0] * al0 + rs0;  mrow[mt][0] = nm0;
            lrow[mt][1] = lrow[mt][1] * al1 + rs1;  mrow[mt][1] = nm1;
#pragma unroll
            for (int n = 0; n < 8; n++) {
                oacc[mt][n][0] *= al0; oacc[mt][n][1] *= al0;
                oacc[mt][n][2] *= al1; oacc[mt][n][3] *= al1;
            }
        }

#pragma unroll
        for (int mt = 0; mt < 2; mt++) {
            int pr0 = (wrow + mt * 16 + r0) * APAD;
            int pr1 = pr0 + 8 * APAD;
#pragma unroll
            for (int n = 0; n < 8; n++) {
                int c = n * 8 + cq * 2;
                *(float2*)&Ps[pr0 + c] =
                    make_float2(f2tf_f(sacc[mt][n][0]), f2tf_f(sacc[mt][n][1]));
                *(float2*)&Ps[pr1 + c] =
                    make_float2(f2tf_f(sacc[mt][n][2]), f2tf_f(sacc[mt][n][3]));
            }
        }
        __syncwarp();

#pragma unroll
        for (int k = 0; k < 8; k++) {
            uint32_t p0[4], p1[4];
            ldsm4(p0[0], p0[1], p0[2], p0[3], ps_a + k * 32);
            ldsm4(p1[0], p1[1], p1[2], p1[3], ps_a + MT_STEP + k * 32);
#pragma unroll
            for (int n = 0; n < 8; n++) {
                uint32_t b0, b1;
                ldsm2(b0, b1, vt_b + n * N_STEP + k * 32);
                mma_tf32(oacc[0][n], p0[0], p0[1], p0[2], p0[3], b0, b1);
                mma_tf32(oacc[1][n], p1[0], p1[1], p1[2], p1[3], b0, b1);
            }
        }
        __syncthreads();
    }

#pragma unroll
    for (int mt = 0; mt < 2; mt++) {
        float inv0 = 1.0f / lrow[mt][0];
        float inv1 = 1.0f / lrow[mt][1];
        int row = q0 + wrow + mt * 16 + r0;
#pragma unroll
        for (int n = 0; n < 8; n++) {
            int col = h * HDn + n * 8 + cq * 2;
            float* p0 = &ctx[((size_t)b * Tn + row) * En + col];
            *(float2*)p0 = make_float2(oacc[mt][n][0] * inv0,
                                       oacc[mt][n][1] * inv0);
            float* p1 = &ctx[((size_t)b * Tn + row + 8) * En + col];
            *(float2*)p1 = make_float2(oacc[mt][n][2] * inv1,
                                       oacc[mt][n][3] * inv1);
        }
    }
}

// ---------------------------------------------------------------------------
extern "C" void kernel_launch(void* const* d_in, const int* in_sizes, int n_in,
                              void* d_out, int out_size) {
    const float*         x      = (const float*)d_in[0];
    const unsigned char* mask   = (const unsigned char*)d_in[1];
    const float*         qkv_w  = (const float*)d_in[2];
    const float*         qkv_b  = (const float*)d_in[3];
    const float*         proj_w = (const float*)d_in[4];
    const float*         proj_b = (const float*)d_in[5];
    float*               out    = (float*)d_out;

    float *qkv_s, *ctx_s;
    cudaGetSymbolAddress((void**)&qkv_s, g_qkv);
    cudaGetSymbolAddress((void**)&ctx_s, g_ctx);

    cudaFuncSetAttribute(gemm_tf32,
                         cudaFuncAttributeMaxDynamicSharedMemorySize,
                         GEMM_TF32_SMEM);
    cudaFuncSetAttribute(attn_tc,
                         cudaFuncAttributeMaxDynamicSharedMemorySize, ATTN3_SMEM);

    // 1) QKV GEMM (tf32 direct, no splits)
    {
        dim3 grid(QKVN / 128, Mn / 128);
        gemm_tf32<<<grid, 256, GEMM_TF32_SMEM>>>(x, qkv_w, qkv_b, qkv_s, QKVN);
    }

    // 2) attention (round-9 config: 4 warps, M=32/warp, 128 q-rows/block)
    {
        dim3 grid(Tn / 128, Bn * Hn);
        attn_tc<<<grid, 128, ATTN3_SMEM>>>(qkv_s, mask, ctx_s);
    }

    // 3) proj GEMM (tf32 direct)
    {
        dim3 grid(En / 128, Mn / 128);
        gemm_tf32<<<grid, 256, GEMM_TF32_SMEM>>>(ctx_s, proj_w, proj_b, out, En);
    }
}

// round 12
// speedup vs baseline: 1.2602x; 1.0992x over previous
#include <cuda_runtime.h>
#include <cuda_bf16.h>
#include <stdint.h>
#include <math.h>

#define Bn   4
#define Tn   2048
#define En   1024
#define Hn   16
#define HDn  64
#define Mn   (Bn * Tn)          // 8192
#define QKVN (3 * En)           // 3072

// ---------------- scratch (__device__ globals; no cudaMalloc allowed) -------
__device__ float g_qkv[(size_t)Mn * QKVN];            // 96 MB fp32
__device__ float g_ctx[(size_t)Mn * En];              // 32 MB (tf32-rounded)
__device__ float g_xr [(size_t)Mn * En];              // 32 MB x rounded
__device__ float g_wr [(size_t)QKVN * En];            // 12 MB qkv_w rounded
__device__ float g_pwr[(size_t)En * En];              //  4 MB proj_w rounded

// ---------------- helpers ----------------------------------------------------
__device__ __forceinline__ uint32_t smem_u32(const void* p) {
    uint32_t a;
    asm("{ .reg .u64 t; cvta.to.shared.u64 t, %1; cvt.u32.u64 %0, t; }"
        : "=r"(a) : "l"(p));
    return a;
}
__device__ __forceinline__ void cp16(uint32_t saddr, const void* g) {
    asm volatile("cp.async.cg.shared.global [%0], [%1], 16;"
                 :: "r"(saddr), "l"(g));
}
template <int N>
__device__ __forceinline__ void cp_wait() {
    asm volatile("cp.async.wait_group %0;" :: "n"(N) : "memory");
}
__device__ __forceinline__ void cp_commit() {
    asm volatile("cp.async.commit_group;" ::: "memory");
}
__device__ __forceinline__ void ldsm4(uint32_t& r0, uint32_t& r1,
                                      uint32_t& r2, uint32_t& r3,
                                      uint32_t addr) {
    asm volatile("ldmatrix.sync.aligned.m8n8.x4.shared.b16 {%0,%1,%2,%3}, [%4];"
                 : "=r"(r0), "=r"(r1), "=r"(r2), "=r"(r3) : "r"(addr));
}
__device__ __forceinline__ void ldsm2(uint32_t& r0, uint32_t& r1,
                                      uint32_t addr) {
    asm volatile("ldmatrix.sync.aligned.m8n8.x2.shared.b16 {%0,%1}, [%2];"
                 : "=r"(r0), "=r"(r1) : "r"(addr));
}
__device__ __forceinline__ uint32_t sw128(uint32_t off) {
    return off ^ ((off >> 3) & 0x70);
}
// tf32 helpers
__device__ __forceinline__ uint32_t f2tf(float x) {
    uint32_t r;
    asm("cvt.rna.tf32.f32 %0, %1;" : "=r"(r) : "f"(x));
    return r;
}
__device__ __forceinline__ float f2tf_f(float x) {
    return __uint_as_float(f2tf(x));
}
__device__ __forceinline__ void mma_tf32(float* d, uint32_t a0, uint32_t a1,
                                         uint32_t a2, uint32_t a3,
                                         uint32_t b0, uint32_t b1) {
    asm volatile(
        "mma.sync.aligned.m16n8k8.row.col.f32.tf32.tf32.f32 "
        "{%0,%1,%2,%3}, {%4,%5,%6,%7}, {%8,%9}, {%0,%1,%2,%3};"
        : "+f"(d[0]), "+f"(d[1]), "+f"(d[2]), "+f"(d[3])
        : "r"(a0), "r"(a1), "r"(a2), "r"(a3), "r"(b0), "r"(b1));
}

// ---------------------------------------------------------------------------
// Elementwise tf32 pre-round (RNA): out[i] = tf32(in[i]) stored as fp32.
// ---------------------------------------------------------------------------
__global__ void roundcvt(const float* __restrict__ in, float* __restrict__ out) {
    size_t i = ((size_t)blockIdx.x * blockDim.x + threadIdx.x) * 4;
    float4 v = *(const float4*)(in + i);
    v.x = f2tf_f(v.x); v.y = f2tf_f(v.y);
    v.z = f2tf_f(v.z); v.w = f2tf_f(v.w);
    *(float4*)(out + i) = v;
}

// ---------------------------------------------------------------------------
// tf32 GEMM with cp.async fill (operands pre-rounded to tf32-in-fp32):
// C[M,Np] = A[M,1024] @ W[Np,1024]^T + bias.
// CTA 128x128, BK=32 floats (128B/row, SW128), double-buffered cp.async.
// 8 warps (4m x 2n), warp tile 32x64; ldmatrix tf32-as-8x4 fragments.
// Swizzle folds to per-lane XOR: every fragment row == lane&7 (mod 8),
// so addr = rowoff + ((col_bytes) ^ ((lane&7)<<4)).
// ---------------------------------------------------------------------------
#define GEMM_SMEM (2 * 32768)   // 2 stages x (A 16KB + B 16KB)

__global__ __launch_bounds__(256, 2)
void gemm_tf32ca(const float* __restrict__ A, const float* __restrict__ W,
                 const float* __restrict__ bias, float* __restrict__ C,
                 int Np) {
    extern __shared__ char gsm[];
    uint32_t sb = smem_u32(gsm);
    const int K = 1024;

    int tid = threadIdx.x;
    int lane = tid & 31;
    int wid = tid >> 5;
    int wm = wid & 3;                 // m offset wm*32
    int wn = wid >> 2;                // n offset wn*64
    int m0 = blockIdx.y * 128;
    int n0 = blockIdx.x * 128;

    // cp.async fill slots: per tile 128 rows x 8 chunks x 16B; 4 per thread
    uint32_t a_soff[4], b_soff[4];
    const char* a_g[4]; const char* b_g[4];
#pragma unroll
    for (int i = 0; i < 4; i++) {
        int c = tid + i * 256;        // 0..1023
        int row = c >> 3, ch = c & 7;
        uint32_t off = row * 128 + ch * 16;
        a_soff[i] = sw128(off);
        b_soff[i] = sw128(off) + 16384;
        a_g[i] = (const char*)(A + (size_t)(m0 + row) * K + ch * 4);
        b_g[i] = (const char*)(W + (size_t)(n0 + row) * K + ch * 4);
    }

    // fragment lane bases
    int t = lane >> 3;
    uint32_t xm = (uint32_t)((lane & 7) << 4);
    uint32_t a_row = (uint32_t)((wm * 32 + (t & 1) * 8 + (lane & 7)) * 128);
    uint32_t a_csel = (uint32_t)((t >> 1) * 16);
    uint32_t b_row = 16384u + (uint32_t)((wn * 64 + (lane & 7)) * 128);
    uint32_t b_csel = (uint32_t)(((lane >> 3) & 1) * 16);

    float acc[2][8][4];
#pragma unroll
    for (int mt = 0; mt < 2; mt++)
#pragma unroll
        for (int nt = 0; nt < 8; nt++)
#pragma unroll
            for (int j = 0; j < 4; j++) acc[mt][nt][j] = 0.0f;

    const int NS = K / 32;            // 32 stages

    // prologue: stages 0,1
#pragma unroll
    for (int s = 0; s < 2; s++) {
        uint32_t base = sb + s * 32768;
        size_t goff = (size_t)s * 128;   // 32 floats = 128 B per stage
#pragma unroll
        for (int i = 0; i < 4; i++) cp16(base + a_soff[i], a_g[i] + goff);
#pragma unroll
        for (int i = 0; i < 4; i++) cp16(base + b_soff[i], b_g[i] + goff);
        cp_commit();
    }

    for (int s = 0; s < NS; s++) {
        if (s == NS - 1) cp_wait<0>(); else cp_wait<1>();
        __syncthreads();

        int buf = s & 1;
        uint32_t base = sb + buf * 32768;
#pragma unroll
        for (int kk = 0; kk < 4; kk++) {
            uint32_t a0[4], a1[4];
            uint32_t ac = ((uint32_t)(kk * 32) + a_csel) ^ xm;
            ldsm4(a0[0], a0[1], a0[2], a0[3], base + a_row + ac);
            ldsm4(a1[0], a1[1], a1[2], a1[3], base + a_row + 2048 + ac);
            uint32_t bc = ((uint32_t)(kk * 32) + b_csel) ^ xm;
#pragma unroll
            for (int nt = 0; nt < 8; nt++) {
                uint32_t b0, b1;
                ldsm2(b0, b1, base + b_row + nt * 1024 + bc);
                mma_tf32(acc[0][nt], a0[0], a0[1], a0[2], a0[3], b0, b1);
                mma_tf32(acc[1][nt], a1[0], a1[1], a1[2], a1[3], b0, b1);
            }
        }
        __syncthreads();

        if (s + 2 < NS) {
            uint32_t nbase = sb + buf * 32768;
            size_t goff = (size_t)(s + 2) * 128;
#pragma unroll
            for (int i = 0; i < 4; i++) cp16(nbase + a_soff[i], a_g[i] + goff);
#pragma unroll
            for (int i = 0; i < 4; i++) cp16(nbase + b_soff[i], b_g[i] + goff);
            cp_commit();
        }
    }

    // epilogue
#pragma unroll
    for (int mt = 0; mt < 2; mt++) {
#pragma unroll
        for (int nt = 0; nt < 8; nt++) {
            int row = m0 + wm * 32 + mt * 16 + (lane >> 2);
            int col = n0 + wn * 64 + nt * 8 + (lane & 3) * 2;
            float2 bv = *(const float2*)(bias + col);
            float* p0 = C + (size_t)row * Np + col;
            *(float2*)p0 = make_float2(acc[mt][nt][0] + bv.x,
                                       acc[mt][nt][1] + bv.y);
            float* p1 = p0 + 8 * (size_t)Np;
            *(float2*)p1 = make_float2(acc[mt][nt][2] + bv.x,
                                       acc[mt][nt][3] + bv.y);
        }
    }
}

// ---------------------------------------------------------------------------
// Flash attention — round-9 version (best measured: 603 us), with ctx
// epilogue pre-rounded to tf32 (feeds proj GEMM's raw-truncation path).
// ---------------------------------------------------------------------------
#define APAD 68
#define ATTN3_SMEM ((128 * APAD + 64 * APAD + 128 * APAD + 64 * APAD + 64) * 4)

__global__ __launch_bounds__(128)
void attn_tc(const float* __restrict__ qkv,
             const unsigned char* __restrict__ mask,
             float* __restrict__ ctx) {
    extern __shared__ float sm2[];
    float* Qs = sm2;                    // [128][APAD]
    float* Ks = Qs + 128 * APAD;        // [64][APAD]
    float* Ps = Ks + 64 * APAD;         // [128][APAD]
    float* Vt = Ps + 128 * APAD;        // [64][APAD]  Vt[d][kv]
    float* Ms = Vt + 64 * APAD;         // [64]

    int tid = threadIdx.x;
    int lane = tid & 31;
    int w = tid >> 5;
    int b  = blockIdx.y >> 4;
    int h  = blockIdx.y & 15;
    int q0 = blockIdx.x * 128;
    int wrow = w * 32;

    const float* qb = qkv + (size_t)b * Tn * QKVN + h * HDn;
    const float* kb = qb + En;
    const float* vb = qb + 2 * En;

#pragma unroll
    for (int it = 0; it < 16; it++) {
        int idx = tid + it * 128;
        int r = idx >> 4;
        int c4 = (idx & 15) * 4;
        float4 v = *(const float4*)(qb + (size_t)(q0 + r) * QKVN + c4);
        v.x = f2tf_f(v.x * 0.125f); v.y = f2tf_f(v.y * 0.125f);
        v.z = f2tf_f(v.z * 0.125f); v.w = f2tf_f(v.w * 0.125f);
        *(float4*)&Qs[r * APAD + c4] = v;
    }

    int r0 = lane >> 2;
    int cq = lane & 3;

    uint32_t sb = smem_u32(sm2);
    int t  = lane >> 3;
    int arow = (t & 1) * 8 + (lane & 7);
    int acol = (t >> 1) * 4;
    uint32_t qs_a = sb + (uint32_t)(((wrow + arow) * APAD + acol) * 4);
    uint32_t ps_a = sb + (uint32_t)((128 * APAD + 64 * APAD) * 4)
                       + (uint32_t)(((wrow + arow) * APAD + acol) * 4);
    int brow = lane & 7;
    int bsel = (lane >> 3) & 1;
    uint32_t ks_b = sb + (uint32_t)((128 * APAD) * 4)
                       + (uint32_t)((brow * APAD + bsel * 4) * 4);
    uint32_t vt_b = sb + (uint32_t)((128 * APAD + 64 * APAD + 128 * APAD) * 4)
                       + (uint32_t)((brow * APAD + bsel * 4) * 4);
    const uint32_t MT_STEP = 16 * APAD * 4;
    const uint32_t N_STEP  = 8 * APAD * 4;

    float oacc[2][8][4];
#pragma unroll
    for (int mt = 0; mt < 2; mt++)
#pragma unroll
        for (int n = 0; n < 8; n++)
#pragma unroll
            for (int j = 0; j < 4; j++) oacc[mt][n][j] = 0.0f;
    float mrow[2][2] = {{-1e30f, -1e30f}, {-1e30f, -1e30f}};
    float lrow[2][2] = {{0.0f, 0.0f}, {0.0f, 0.0f}};

    for (int kv0 = 0; kv0 < Tn; kv0 += 64) {
#pragma unroll
        for (int it = 0; it < 8; it++) {
            int idx = tid + it * 128;
            int r = idx >> 4;
            int c4 = (idx & 15) * 4;
            float4 v = *(const float4*)(kb + (size_t)(kv0 + r) * QKVN + c4);
            v.x = f2tf_f(v.x); v.y = f2tf_f(v.y);
            v.z = f2tf_f(v.z); v.w = f2tf_f(v.w);
            *(float4*)&Ks[r * APAD + c4] = v;
        }
#pragma unroll
        for (int it = 0; it < 8; it++) {
            int idx = tid + it * 128;
            int r = idx & 63;
            int c4 = (idx >> 6) * 4;
            float4 v = *(const float4*)(vb + (size_t)(kv0 + r) * QKVN + c4);
            Vt[(c4 + 0) * APAD + r] = f2tf_f(v.x);
            Vt[(c4 + 1) * APAD + r] = f2tf_f(v.y);
            Vt[(c4 + 2) * APAD + r] = f2tf_f(v.z);
            Vt[(c4 + 3) * APAD + r] = f2tf_f(v.w);
        }
        if (tid < 64)
            Ms[tid] = mask[b * Tn + kv0 + tid] ? -1e30f : 0.0f;
        __syncthreads();

        float sacc[2][8][4];
#pragma unroll
        for (int mt = 0; mt < 2; mt++)
#pragma unroll
            for (int n = 0; n < 8; n++)
#pragma unroll
                for (int j = 0; j < 4; j++) sacc[mt][n][j] = 0.0f;

#pragma unroll
        for (int k = 0; k < 8; k++) {
            uint32_t a0[4], a1[4];
            ldsm4(a0[0], a0[1], a0[2], a0[3], qs_a + k * 32);
            ldsm4(a1[0], a1[1], a1[2], a1[3], qs_a + MT_STEP + k * 32);
#pragma unroll
            for (int n = 0; n < 8; n++) {
                uint32_t b0, b1;
                ldsm2(b0, b1, ks_b + n * N_STEP + k * 32);
                mma_tf32(sacc[0][n], a0[0], a0[1], a0[2], a0[3], b0, b1);
                mma_tf32(sacc[1][n], a1[0], a1[1], a1[2], a1[3], b0, b1);
            }
        }

#pragma unroll
        for (int mt = 0; mt < 2; mt++) {
            float mx0 = -1e30f, mx1 = -1e30f;
#pragma unroll
            for (int n = 0; n < 8; n++) {
                int c = n * 8 + cq * 2;
                float ma = Ms[c], mb2 = Ms[c + 1];
                sacc[mt][n][0] += ma; sacc[mt][n][1] += mb2;
                sacc[mt][n][2] += ma; sacc[mt][n][3] += mb2;
                mx0 = fmaxf(mx0, fmaxf(sacc[mt][n][0], sacc[mt][n][1]));
                mx1 = fmaxf(mx1, fmaxf(sacc[mt][n][2], sacc[mt][n][3]));
            }
            mx0 = fmaxf(mx0, __shfl_xor_sync(0xffffffffu, mx0, 1));
            mx0 = fmaxf(mx0, __shfl_xor_sync(0xffffffffu, mx0, 2));
            mx1 = fmaxf(mx1, __shfl_xor_sync(0xffffffffu, mx1, 1));
            mx1 = fmaxf(mx1, __shfl_xor_sync(0xffffffffu, mx1, 2));

            float nm0 = fmaxf(mrow[mt][0], mx0);
            float nm1 = fmaxf(mrow[mt][1], mx1);
            float al0 = __expf(mrow[mt][0] - nm0);
            float al1 = __expf(mrow[mt][1] - nm1);
            float rs0 = 0.0f, rs1 = 0.0f;
#pragma unroll
            for (int n = 0; n < 8; n++) {
                sacc[mt][n][0] = __expf(sacc[mt][n][0] - nm0);
                sacc[mt][n][1] = __expf(sacc[mt][n][1] - nm0);
                sacc[mt][n][2] = __expf(sacc[mt][n][2] - nm1);
                sacc[mt][n][3] = __expf(sacc[mt][n][3] - nm1);
                rs0 += sacc[mt][n][0] + sacc[mt][n][1];
                rs1 += sacc[mt][n][2] + sacc[mt][n][3];
            }
            rs0 += __shfl_xor_sync(0xffffffffu, rs0, 1);
            rs0 += __shfl_xor_sync(0xffffffffu, rs0, 2);
            rs1 += __shfl_xor_sync(0xffffffffu, rs1, 1);
            rs1 += __shfl_xor_sync(0xffffffffu, rs1, 2);

            lrow[mt][0] = lrow[mt][0] * al0 + rs0;  mrow[mt][0] = nm0;
            lrow[mt][1] = lrow[mt][1] * al1 + rs1;  mrow[mt][1] = nm1;
#pragma unroll
            for (int n = 0; n < 8; n++) {
                oacc[mt][n][0] *= al0; oacc[mt][n][1] *= al0;
                oacc[mt][n][2] *= al1; oacc[mt][n][3] *= al1;
            }
        }

#pragma unroll
        for (int mt = 0; mt < 2; mt++) {
            int pr0 = (wrow + mt * 16 + r0) * APAD;
            int pr1 = pr0 + 8 * APAD;
#pragma unroll
            for (int n = 0; n < 8; n++) {
                int c = n * 8 + cq * 2;
                *(float2*)&Ps[pr0 + c] =
                    make_float2(f2tf_f(sacc[mt][n][0]), f2tf_f(sacc[mt][n][1]));
                *(float2*)&Ps[pr1 + c] =
                    make_float2(f2tf_f(sacc[mt][n][2]), f2tf_f(sacc[mt][n][3]));
            }
        }
        __syncwarp();

#pragma unroll
        for (int k = 0; k < 8; k++) {
            uint32_t p0[4], p1[4];
            ldsm4(p0[0], p0[1], p0[2], p0[3], ps_a + k * 32);
            ldsm4(p1[0], p1[1], p1[2], p1[3], ps_a + MT_STEP + k * 32);
#pragma unroll
            for (int n = 0; n < 8; n++) {
                uint32_t b0, b1;
                ldsm2(b0, b1, vt_b + n * N_STEP + k * 32);
                mma_tf32(oacc[0][n], p0[0], p0[1], p0[2], p0[3], b0, b1);
                mma_tf32(oacc[1][n], p1[0], p1[1], p1[2], p1[3], b0, b1);
            }
        }
        __syncthreads();
    }

#pragma unroll
    for (int mt = 0; mt < 2; mt++) {
        float inv0 = 1.0f / lrow[mt][0];
        float inv1 = 1.0f / lrow[mt][1];
        int row = q0 + wrow + mt * 16 + r0;
#pragma unroll
        for (int n = 0; n < 8; n++) {
            int col = h * HDn + n * 8 + cq * 2;
            float* p0 = &ctx[((size_t)b * Tn + row) * En + col];
            *(float2*)p0 = make_float2(f2tf_f(oacc[mt][n][0] * inv0),
                                       f2tf_f(oacc[mt][n][1] * inv0));
            float* p1 = &ctx[((size_t)b * Tn + row + 8) * En + col];
            *(float2*)p1 = make_float2(f2tf_f(oacc[mt][n][2] * inv1),
                                       f2tf_f(oacc[mt][n][3] * inv1));
        }
    }
}

// ---------------------------------------------------------------------------
extern "C" void kernel_launch(void* const* d_in, const int* in_sizes, int n_in,
                              void* d_out, int out_size) {
    const float*         x      = (const float*)d_in[0];
    const unsigned char* mask   = (const unsigned char*)d_in[1];
    const float*         qkv_w  = (const float*)d_in[2];
    const float*         qkv_b  = (const float*)d_in[3];
    const float*         proj_w = (const float*)d_in[4];
    const float*         proj_b = (const float*)d_in[5];
    float*               out    = (float*)d_out;

    float *qkv_s, *ctx_s, *xr, *wr, *pwr;
    cudaGetSymbolAddress((void**)&qkv_s, g_qkv);
    cudaGetSymbolAddress((void**)&ctx_s, g_ctx);
    cudaGetSymbolAddress((void**)&xr,  g_xr);
    cudaGetSymbolAddress((void**)&wr,  g_wr);
    cudaGetSymbolAddress((void**)&pwr, g_pwr);

    cudaFuncSetAttribute(gemm_tf32ca,
                         cudaFuncAttributeMaxDynamicSharedMemorySize, GEMM_SMEM);
    cudaFuncSetAttribute(attn_tc,
                         cudaFuncAttributeMaxDynamicSharedMemorySize, ATTN3_SMEM);

    // 0) pre-round operands to tf32-in-fp32 (RNA; exact feed for raw mma)
    roundcvt<<<(size_t)Mn * En / 4 / 256, 256>>>(x, xr);
    roundcvt<<<(size_t)QKVN * En / 4 / 256, 256>>>(qkv_w, wr);
    roundcvt<<<(size_t)En * En / 4 / 256, 256>>>(proj_w, pwr);

    // 1) QKV GEMM (cp.async tf32)
    {
        dim3 grid(QKVN / 128, Mn / 128);
        gemm_tf32ca<<<grid, 256, GEMM_SMEM>>>(xr, wr, qkv_b, qkv_s, QKVN);
    }

    // 2) attention (round-9 config; ctx written tf32-rounded)
    {
        dim3 grid(Tn / 128, Bn * Hn);
        attn_tc<<<grid, 128, ATTN3_SMEM>>>(qkv_s, mask, ctx_s);
    }

    // 3) proj GEMM (cp.async tf32; ctx already rounded by attn epilogue)
    {
        dim3 grid(En / 128, Mn / 128);
        gemm_tf32ca<<<grid, 256, GEMM_SMEM>>>(ctx_s, pwr, proj_b, out, En);
    }
}

// round 13
// speedup vs baseline: 1.3398x; 1.0632x over previous
#include <cuda_runtime.h>
#include <cuda_bf16.h>
#include <stdint.h>
#include <math.h>

#define Bn   4
#define Tn   2048
#define En   1024
#define Hn   16
#define HDn  64
#define Mn   (Bn * Tn)          // 8192
#define QKVN (3 * En)           // 3072

// ---------------- scratch (__device__ globals; no cudaMalloc allowed) -------
__device__ float g_qkv[(size_t)Mn * QKVN];            // 96 MB fp32
__device__ float g_ctx[(size_t)Mn * En];              // 32 MB (tf32-rounded)
__device__ float g_xr [(size_t)Mn * En];              // 32 MB x rounded
__device__ float g_wr [(size_t)QKVN * En];            // 12 MB qkv_w rounded
__device__ float g_pwr[(size_t)En * En];              //  4 MB proj_w rounded

// ---------------- helpers ----------------------------------------------------
__device__ __forceinline__ uint32_t smem_u32(const void* p) {
    uint32_t a;
    asm("{ .reg .u64 t; cvta.to.shared.u64 t, %1; cvt.u32.u64 %0, t; }"
        : "=r"(a) : "l"(p));
    return a;
}
__device__ __forceinline__ void cp16(uint32_t saddr, const void* g) {
    asm volatile("cp.async.cg.shared.global [%0], [%1], 16;"
                 :: "r"(saddr), "l"(g));
}
template <int N>
__device__ __forceinline__ void cp_wait() {
    asm volatile("cp.async.wait_group %0;" :: "n"(N) : "memory");
}
__device__ __forceinline__ void cp_commit() {
    asm volatile("cp.async.commit_group;" ::: "memory");
}
__device__ __forceinline__ void ldsm4(uint32_t& r0, uint32_t& r1,
                                      uint32_t& r2, uint32_t& r3,
                                      uint32_t addr) {
    asm volatile("ldmatrix.sync.aligned.m8n8.x4.shared.b16 {%0,%1,%2,%3}, [%4];"
                 : "=r"(r0), "=r"(r1), "=r"(r2), "=r"(r3) : "r"(addr));
}
__device__ __forceinline__ void ldsm2(uint32_t& r0, uint32_t& r1,
                                      uint32_t addr) {
    asm volatile("ldmatrix.sync.aligned.m8n8.x2.shared.b16 {%0,%1}, [%2];"
                 : "=r"(r0), "=r"(r1) : "r"(addr));
}
__device__ __forceinline__ uint32_t sw128(uint32_t off) {
    return off ^ ((off >> 3) & 0x70);
}
// tf32 helpers
__device__ __forceinline__ uint32_t f2tf(float x) {
    uint32_t r;
    asm("cvt.rna.tf32.f32 %0, %1;" : "=r"(r) : "f"(x));
    return r;
}
__device__ __forceinline__ float f2tf_f(float x) {
    return __uint_as_float(f2tf(x));
}
__device__ __forceinline__ void mma_tf32(float* d, uint32_t a0, uint32_t a1,
                                         uint32_t a2, uint32_t a3,
                                         uint32_t b0, uint32_t b1) {
    asm volatile(
        "mma.sync.aligned.m16n8k8.row.col.f32.tf32.tf32.f32 "
        "{%0,%1,%2,%3}, {%4,%5,%6,%7}, {%8,%9}, {%0,%1,%2,%3};"
        : "+f"(d[0]), "+f"(d[1]), "+f"(d[2]), "+f"(d[3])
        : "r"(a0), "r"(a1), "r"(a2), "r"(a3), "r"(b0), "r"(b1));
}

// ---------------------------------------------------------------------------
// Elementwise tf32 pre-round (RNA)
// ---------------------------------------------------------------------------
__global__ void roundcvt(const float* __restrict__ in, float* __restrict__ out) {
    size_t i = ((size_t)blockIdx.x * blockDim.x + threadIdx.x) * 4;
    float4 v = *(const float4*)(in + i);
    v.x = f2tf_f(v.x); v.y = f2tf_f(v.y);
    v.z = f2tf_f(v.z); v.w = f2tf_f(v.w);
    *(float4*)(out + i) = v;
}

// ---------------------------------------------------------------------------
// tf32 GEMM with cp.async fill (round-12, verified: 249us QKV, tensor 67.8%)
// ---------------------------------------------------------------------------
#define GEMM_SMEM (2 * 32768)

__global__ __launch_bounds__(256, 2)
void gemm_tf32ca(const float* __restrict__ A, const float* __restrict__ W,
                 const float* __restrict__ bias, float* __restrict__ C,
                 int Np) {
    extern __shared__ char gsm[];
    uint32_t sb = smem_u32(gsm);
    const int K = 1024;

    int tid = threadIdx.x;
    int lane = tid & 31;
    int wid = tid >> 5;
    int wm = wid & 3;
    int wn = wid >> 2;
    int m0 = blockIdx.y * 128;
    int n0 = blockIdx.x * 128;

    uint32_t a_soff[4], b_soff[4];
    const char* a_g[4]; const char* b_g[4];
#pragma unroll
    for (int i = 0; i < 4; i++) {
        int c = tid + i * 256;
        int row = c >> 3, ch = c & 7;
        uint32_t off = row * 128 + ch * 16;
        a_soff[i] = sw128(off);
        b_soff[i] = sw128(off) + 16384;
        a_g[i] = (const char*)(A + (size_t)(m0 + row) * K + ch * 4);
        b_g[i] = (const char*)(W + (size_t)(n0 + row) * K + ch * 4);
    }

    int t = lane >> 3;
    uint32_t xm = (uint32_t)((lane & 7) << 4);
    uint32_t a_row = (uint32_t)((wm * 32 + (t & 1) * 8 + (lane & 7)) * 128);
    uint32_t a_csel = (uint32_t)((t >> 1) * 16);
    uint32_t b_row = 16384u + (uint32_t)((wn * 64 + (lane & 7)) * 128);
    uint32_t b_csel = (uint32_t)(((lane >> 3) & 1) * 16);

    float acc[2][8][4];
#pragma unroll
    for (int mt = 0; mt < 2; mt++)
#pragma unroll
        for (int nt = 0; nt < 8; nt++)
#pragma unroll
            for (int j = 0; j < 4; j++) acc[mt][nt][j] = 0.0f;

    const int NS = K / 32;

#pragma unroll
    for (int s = 0; s < 2; s++) {
        uint32_t base = sb + s * 32768;
        size_t goff = (size_t)s * 128;
#pragma unroll
        for (int i = 0; i < 4; i++) cp16(base + a_soff[i], a_g[i] + goff);
#pragma unroll
        for (int i = 0; i < 4; i++) cp16(base + b_soff[i], b_g[i] + goff);
        cp_commit();
    }

    for (int s = 0; s < NS; s++) {
        if (s == NS - 1) cp_wait<0>(); else cp_wait<1>();
        __syncthreads();

        int buf = s & 1;
        uint32_t base = sb + buf * 32768;
#pragma unroll
        for (int kk = 0; kk < 4; kk++) {
            uint32_t a0[4], a1[4];
            uint32_t ac = ((uint32_t)(kk * 32) + a_csel) ^ xm;
            ldsm4(a0[0], a0[1], a0[2], a0[3], base + a_row + ac);
            ldsm4(a1[0], a1[1], a1[2], a1[3], base + a_row + 2048 + ac);
            uint32_t bc = ((uint32_t)(kk * 32) + b_csel) ^ xm;
#pragma unroll
            for (int nt = 0; nt < 8; nt++) {
                uint32_t b0, b1;
                ldsm2(b0, b1, base + b_row + nt * 1024 + bc);
                mma_tf32(acc[0][nt], a0[0], a0[1], a0[2], a0[3], b0, b1);
                mma_tf32(acc[1][nt], a1[0], a1[1], a1[2], a1[3], b0, b1);
            }
        }
        __syncthreads();

        if (s + 2 < NS) {
            uint32_t nbase = sb + buf * 32768;
            size_t goff = (size_t)(s + 2) * 128;
#pragma unroll
            for (int i = 0; i < 4; i++) cp16(nbase + a_soff[i], a_g[i] + goff);
#pragma unroll
            for (int i = 0; i < 4; i++) cp16(nbase + b_soff[i], b_g[i] + goff);
            cp_commit();
        }
    }

#pragma unroll
    for (int mt = 0; mt < 2; mt++) {
#pragma unroll
        for (int nt = 0; nt < 8; nt++) {
            int row = m0 + wm * 32 + mt * 16 + (lane >> 2);
            int col = n0 + wn * 64 + nt * 8 + (lane & 3) * 2;
            float2 bv = *(const float2*)(bias + col);
            float* p0 = C + (size_t)row * Np + col;
            *(float2*)p0 = make_float2(acc[mt][nt][0] + bv.x,
                                       acc[mt][nt][1] + bv.y);
            float* p1 = p0 + 8 * (size_t)Np;
            *(float2*)p1 = make_float2(acc[mt][nt][2] + bv.x,
                                       acc[mt][nt][3] + bv.y);
        }
    }
}

// ---------------------------------------------------------------------------
// Flash attention, tf32 HMMA. Register P-reuse: S accumulator fragment
// (c0,c2,c1,c3) used directly as PV A-fragment; V stored with per-8-block
// kv-row permutation pk(r) = (r>>1) | ((r&1)*4), so no Ps smem round-trip.
// Block = 128 threads / 4 warps; warp M-tile = 32 q rows; KV tiles of 64.
// smem: Qs[128][68], Ks[64][68], Vt[64][68], Ms[64]  (~70KB)
// ---------------------------------------------------------------------------
#define APAD 68
#define ATTN4_SMEM ((128 * APAD + 64 * APAD + 64 * APAD + 64) * 4)

__global__ __launch_bounds__(128)
void attn_tc(const float* __restrict__ qkv,
             const unsigned char* __restrict__ mask,
             float* __restrict__ ctx) {
    extern __shared__ float sm2[];
    float* Qs = sm2;                    // [128][APAD]
    float* Ks = Qs + 128 * APAD;        // [64][APAD]
    float* Vt = Ks + 64 * APAD;         // [64][APAD]  Vt[d][pk(kv)]
    float* Ms = Vt + 64 * APAD;         // [64]

    int tid = threadIdx.x;
    int lane = tid & 31;
    int w = tid >> 5;
    int b  = blockIdx.y >> 4;
    int h  = blockIdx.y & 15;
    int q0 = blockIdx.x * 128;
    int wrow = w * 32;

    const float* qb = qkv + (size_t)b * Tn * QKVN + h * HDn;
    const float* kb = qb + En;
    const float* vb = qb + 2 * En;

#pragma unroll
    for (int it = 0; it < 16; it++) {
        int idx = tid + it * 128;
        int r = idx >> 4;
        int c4 = (idx & 15) * 4;
        float4 v = *(const float4*)(qb + (size_t)(q0 + r) * QKVN + c4);
        v.x = f2tf_f(v.x * 0.125f); v.y = f2tf_f(v.y * 0.125f);
        v.z = f2tf_f(v.z * 0.125f); v.w = f2tf_f(v.w * 0.125f);
        *(float4*)&Qs[r * APAD + c4] = v;
    }

    int r0 = lane >> 2;
    int cq = lane & 3;

    uint32_t sb = smem_u32(sm2);
    int t  = lane >> 3;
    int arow = (t & 1) * 8 + (lane & 7);
    int acol = (t >> 1) * 4;
    uint32_t qs_a = sb + (uint32_t)(((wrow + arow) * APAD + acol) * 4);
    int brow = lane & 7;
    int bsel = (lane >> 3) & 1;
    uint32_t ks_b = sb + (uint32_t)((128 * APAD) * 4)
                       + (uint32_t)((brow * APAD + bsel * 4) * 4);
    uint32_t vt_b = sb + (uint32_t)((128 * APAD + 64 * APAD) * 4)
                       + (uint32_t)((brow * APAD + bsel * 4) * 4);
    const uint32_t MT_STEP = 16 * APAD * 4;
    const uint32_t N_STEP  = 8 * APAD * 4;

    float oacc[2][8][4];
#pragma unroll
    for (int mt = 0; mt < 2; mt++)
#pragma unroll
        for (int n = 0; n < 8; n++)
#pragma unroll
            for (int j = 0; j < 4; j++) oacc[mt][n][j] = 0.0f;
    float mrow[2][2] = {{-1e30f, -1e30f}, {-1e30f, -1e30f}};
    float lrow[2][2] = {{0.0f, 0.0f}, {0.0f, 0.0f}};

    for (int kv0 = 0; kv0 < Tn; kv0 += 64) {
        // ---- K fill (tf32, natural layout) ----
#pragma unroll
        for (int it = 0; it < 8; it++) {
            int idx = tid + it * 128;
            int r = idx >> 4;
            int c4 = (idx & 15) * 4;
            float4 v = *(const float4*)(kb + (size_t)(kv0 + r) * QKVN + c4);
            v.x = f2tf_f(v.x); v.y = f2tf_f(v.y);
            v.z = f2tf_f(v.z); v.w = f2tf_f(v.w);
            *(float4*)&Ks[r * APAD + c4] = v;
        }
        // ---- V fill transposed + kv-permuted: Vt[d][pk(r)] ----
#pragma unroll
        for (int it = 0; it < 8; it++) {
            int idx = tid + it * 128;
            int r = idx & 63;                 // kv row
            int c4 = (idx >> 6) * 4;          // d base
            float4 v = *(const float4*)(vb + (size_t)(kv0 + r) * QKVN + c4);
            int pr = (r & ~7) | ((r & 1) << 2) | ((r >> 1) & 3);
            Vt[(c4 + 0) * APAD + pr] = f2tf_f(v.x);
            Vt[(c4 + 1) * APAD + pr] = f2tf_f(v.y);
            Vt[(c4 + 2) * APAD + pr] = f2tf_f(v.z);
            Vt[(c4 + 3) * APAD + pr] = f2tf_f(v.w);
        }
        if (tid < 64)
            Ms[tid] = mask[b * Tn + kv0 + tid] ? -1e30f : 0.0f;
        __syncthreads();

        // ---- S = Q K^T ----
        float sacc[2][8][4];
#pragma unroll
        for (int mt = 0; mt < 2; mt++)
#pragma unroll
            for (int n = 0; n < 8; n++)
#pragma unroll
                for (int j = 0; j < 4; j++) sacc[mt][n][j] = 0.0f;

#pragma unroll
        for (int k = 0; k < 8; k++) {
            uint32_t a0[4], a1[4];
            ldsm4(a0[0], a0[1], a0[2], a0[3], qs_a + k * 32);
            ldsm4(a1[0], a1[1], a1[2], a1[3], qs_a + MT_STEP + k * 32);
#pragma unroll
            for (int n = 0; n < 8; n++) {
                uint32_t b0, b1;
                ldsm2(b0, b1, ks_b + n * N_STEP + k * 32);
                mma_tf32(sacc[0][n], a0[0], a0[1], a0[2], a0[3], b0, b1);
                mma_tf32(sacc[1][n], a1[0], a1[1], a1[2], a1[3], b0, b1);
            }
        }

        // ---- mask + online softmax ----
#pragma unroll
        for (int mt = 0; mt < 2; mt++) {
            float mx0 = -1e30f, mx1 = -1e30f;
#pragma unroll
            for (int n = 0; n < 8; n++) {
                int c = n * 8 + cq * 2;
                float ma = Ms[c], mb2 = Ms[c + 1];
                sacc[mt][n][0] += ma; sacc[mt][n][1] += mb2;
                sacc[mt][n][2] += ma; sacc[mt][n][3] += mb2;
                mx0 = fmaxf(mx0, fmaxf(sacc[mt][n][0], sacc[mt][n][1]));
                mx1 = fmaxf(mx1, fmaxf(sacc[mt][n][2], sacc[mt][n][3]));
            }
            mx0 = fmaxf(mx0, __shfl_xor_sync(0xffffffffu, mx0, 1));
            mx0 = fmaxf(mx0, __shfl_xor_sync(0xffffffffu, mx0, 2));
            mx1 = fmaxf(mx1, __shfl_xor_sync(0xffffffffu, mx1, 1));
            mx1 = fmaxf(mx1, __shfl_xor_sync(0xffffffffu, mx1, 2));

            float nm0 = fmaxf(mrow[mt][0], mx0);
            float nm1 = fmaxf(mrow[mt][1], mx1);
            float al0 = __expf(mrow[mt][0] - nm0);
            float al1 = __expf(mrow[mt][1] - nm1);
            float rs0 = 0.0f, rs1 = 0.0f;
#pragma unroll
            for (int n = 0; n < 8; n++) {
                sacc[mt][n][0] = __expf(sacc[mt][n][0] - nm0);
                sacc[mt][n][1] = __expf(sacc[mt][n][1] - nm0);
                sacc[mt][n][2] = __expf(sacc[mt][n][2] - nm1);
                sacc[mt][n][3] = __expf(sacc[mt][n][3] - nm1);
                rs0 += sacc[mt][n][0] + sacc[mt][n][1];
                rs1 += sacc[mt][n][2] + sacc[mt][n][3];
            }
            rs0 += __shfl_xor_sync(0xffffffffu, rs0, 1);
            rs0 += __shfl_xor_sync(0xffffffffu, rs0, 2);
            rs1 += __shfl_xor_sync(0xffffffffu, rs1, 1);
            rs1 += __shfl_xor_sync(0xffffffffu, rs1, 2);

            lrow[mt][0] = lrow[mt][0] * al0 + rs0;  mrow[mt][0] = nm0;
            lrow[mt][1] = lrow[mt][1] * al1 + rs1;  mrow[mt][1] = nm1;
#pragma unroll
            for (int n = 0; n < 8; n++) {
                oacc[mt][n][0] *= al0; oacc[mt][n][1] *= al0;
                oacc[mt][n][2] *= al1; oacc[mt][n][3] *= al1;
            }
        }

        // ---- O += P V (P from registers; V kv-permuted in smem) ----
        // PV A-fragment = (c0, c2, c1, c3) of the S fragment, tf32-rounded.
#pragma unroll
        for (int k = 0; k < 8; k++) {
            uint32_t p00 = f2tf(sacc[0][k][0]);
            uint32_t p01 = f2tf(sacc[0][k][2]);
            uint32_t p02 = f2tf(sacc[0][k][1]);
            uint32_t p03 = f2tf(sacc[0][k][3]);
            uint32_t p10 = f2tf(sacc[1][k][0]);
            uint32_t p11 = f2tf(sacc[1][k][2]);
            uint32_t p12 = f2tf(sacc[1][k][1]);
            uint32_t p13 = f2tf(sacc[1][k][3]);
#pragma unroll
            for (int n = 0; n < 8; n++) {
                uint32_t b0, b1;
                ldsm2(b0, b1, vt_b + n * N_STEP + k * 32);
                mma_tf32(oacc[0][n], p00, p01, p02, p03, b0, b1);
                mma_tf32(oacc[1][n], p10, p11, p12, p13, b0, b1);
            }
        }
        __syncthreads();
    }

    // ---- epilogue (ctx written tf32-rounded for proj GEMM raw feed) ----
#pragma unroll
    for (int mt = 0; mt < 2; mt++) {
        float inv0 = 1.0f / lrow[mt][0];
        float inv1 = 1.0f / lrow[mt][1];
        int row = q0 + wrow + mt * 16 + r0;
#pragma unroll
        for (int n = 0; n < 8; n++) {
            int col = h * HDn + n * 8 + cq * 2;
            float* p0 = &ctx[((size_t)b * Tn + row) * En + col];
            *(float2*)p0 = make_float2(f2tf_f(oacc[mt][n][0] * inv0),
                                       f2tf_f(oacc[mt][n][1] * inv0));
            float* p1 = &ctx[((size_t)b * Tn + row + 8) * En + col];
            *(float2*)p1 = make_float2(f2tf_f(oacc[mt][n][2] * inv1),
                                       f2tf_f(oacc[mt][n][3] * inv1));
        }
    }
}

// ---------------------------------------------------------------------------
extern "C" void kernel_launch(void* const* d_in, const int* in_sizes, int n_in,
                              void* d_out, int out_size) {
    const float*         x      = (const float*)d_in[0];
    const unsigned char* mask   = (const unsigned char*)d_in[1];
    const float*         qkv_w  = (const float*)d_in[2];
    const float*         qkv_b  = (const float*)d_in[3];
    const float*         proj_w = (const float*)d_in[4];
    const float*         proj_b = (const float*)d_in[5];
    float*               out    = (float*)d_out;

    float *qkv_s, *ctx_s, *xr, *wr, *pwr;
    cudaGetSymbolAddress((void**)&qkv_s, g_qkv);
    cudaGetSymbolAddress((void**)&ctx_s, g_ctx);
    cudaGetSymbolAddress((void**)&xr,  g_xr);
    cudaGetSymbolAddress((void**)&wr,  g_wr);
    cudaGetSymbolAddress((void**)&pwr, g_pwr);

    cudaFuncSetAttribute(gemm_tf32ca,
                         cudaFuncAttributeMaxDynamicSharedMemorySize, GEMM_SMEM);
    cudaFuncSetAttribute(attn_tc,
                         cudaFuncAttributeMaxDynamicSharedMemorySize, ATTN4_SMEM);

    // 0) pre-round operands to tf32-in-fp32
    roundcvt<<<(size_t)Mn * En / 4 / 256, 256>>>(x, xr);
    roundcvt<<<(size_t)QKVN * En / 4 / 256, 256>>>(qkv_w, wr);
    roundcvt<<<(size_t)En * En / 4 / 256, 256>>>(proj_w, pwr);

    // 1) QKV GEMM
    {
        dim3 grid(QKVN / 128, Mn / 128);
        gemm_tf32ca<<<grid, 256, GEMM_SMEM>>>(xr, wr, qkv_b, qkv_s, QKVN);
    }

    // 2) attention (register P-reuse)
    {
        dim3 grid(Tn / 128, Bn * Hn);
        attn_tc<<<grid, 128, ATTN4_SMEM>>>(qkv_s, mask, ctx_s);
    }

    // 3) proj GEMM
    {
        dim3 grid(En / 128, Mn / 128);
        gemm_tf32ca<<<grid, 256, GEMM_SMEM>>>(ctx_s, pwr, proj_b, out, En);
    }
}